// round 1
// baseline (speedup 1.0000x reference)
#include <cuda_runtime.h>
#include <math.h>

#define B_  16
#define NQ  1024
#define D_  512
#define H_  8
#define DH  64
#define M_  (B_*NQ)

__device__ float g_Qp[(size_t)M_*D_];
__device__ float g_Kp[(size_t)M_*D_];
__device__ float g_V [(size_t)M_*D_];
__device__ float g_O1[(size_t)M_*D_];
__device__ float g_O2[(size_t)M_*D_];

#define BM 64
#define BN 64
#define BK 16

template<int EPI>   // 0: (acc+bias)*mask[row]   1: acc+bias   2: A[row,col]+relu(acc+bias)
__global__ void __launch_bounds__(256) gemm_k(
    const float* __restrict__ A, const float* __restrict__ W,
    const float* __restrict__ bias, const float* __restrict__ mask,
    float* __restrict__ C, int M, int N, int K)
{
    __shared__ float As[BK][BM+4];
    __shared__ float Ws[BK][BN];

    const int tid = threadIdx.x;
    const int tx = tid & 15, ty = tid >> 4;
    const int bm = blockIdx.y * BM, bn = blockIdx.x * BN;

    const int arow = tid >> 2;
    const int acol = (tid & 3) << 2;
    const int wrow = tid >> 4;
    const int wcol = (tid & 15) << 2;

    const float* Aptr = A + (size_t)(bm + arow) * K + acol;
    const float* Wptr = W + (size_t)wrow * N + bn + wcol;

    float acc[4][4] = {};

    for (int k0 = 0; k0 < K; k0 += BK) {
        float4 av = *(const float4*)(Aptr + k0);
        As[acol+0][arow] = av.x;
        As[acol+1][arow] = av.y;
        As[acol+2][arow] = av.z;
        As[acol+3][arow] = av.w;
        *(float4*)&Ws[wrow][wcol] = *(const float4*)(Wptr + (size_t)k0 * N);
        __syncthreads();

        #pragma unroll
        for (int kk = 0; kk < BK; kk++) {
            float4 a = *(const float4*)&As[kk][ty<<2];
            float4 b = *(const float4*)&Ws[kk][tx<<2];
            float ar[4] = {a.x, a.y, a.z, a.w};
            float br[4] = {b.x, b.y, b.z, b.w};
            #pragma unroll
            for (int i = 0; i < 4; i++)
                #pragma unroll
                for (int j = 0; j < 4; j++)
                    acc[i][j] += ar[i] * br[j];
        }
        __syncthreads();
    }

    const int row = bm + (ty<<2);
    const int col = bn + (tx<<2);
    const float4 bia = *(const float4*)(bias + col);

    #pragma unroll
    for (int i = 0; i < 4; i++) {
        float r0 = acc[i][0] + bia.x;
        float r1 = acc[i][1] + bia.y;
        float r2 = acc[i][2] + bia.z;
        float r3 = acc[i][3] + bia.w;
        float4 o;
        if (EPI == 0) {
            float mk = mask[row + i];
            o = make_float4(r0*mk, r1*mk, r2*mk, r3*mk);
        } else if (EPI == 1) {
            o = make_float4(r0, r1, r2, r3);
        } else {
            const float4 rv = *(const float4*)(A + (size_t)(row+i)*K + col);
            o = make_float4(rv.x + fmaxf(r0, 0.f),
                            rv.y + fmaxf(r1, 0.f),
                            rv.z + fmaxf(r2, 0.f),
                            rv.w + fmaxf(r3, 0.f));
        }
        *(float4*)&C[(size_t)(row+i)*N + col] = o;
    }
}

#define ATT_SMEM ((3*64*68 + 64*64 + 3*64) * 4)

__global__ void __launch_bounds__(256) attn_k(
    const float* __restrict__ Qp, const float* __restrict__ Kp,
    const float* __restrict__ Vp, const float* __restrict__ Qm,
    const float* __restrict__ Km, float* __restrict__ O)
{
    extern __shared__ float sm[];
    float* Qs  = sm;             // [64][68] (d, q)
    float* Ks  = Qs + 64*68;     // [64][68] (d, k)
    float* Xs  = Ks + 64*68;     // [64][68] (k, q)
    float* Vs  = Xs + 64*68;     // [64][64] (k, d)
    float* Qms = Vs + 64*64;
    float* Kms = Qms + 64;
    float* Rs  = Kms + 64;

    const int tid = threadIdx.x;
    const int tx = tid & 15, ty = tid >> 4;
    const int q0 = blockIdx.x * 64;
    const int b  = blockIdx.y;
    const int h  = blockIdx.z;
    const size_t base = (size_t)b * NQ * D_ + (size_t)h * DH;

    const int lrow = tid >> 2;
    const int lseg = (tid & 3) << 4;

    {
        const float* qr = Qp + base + (size_t)(q0 + lrow) * D_ + lseg;
        #pragma unroll
        for (int u = 0; u < 4; u++) {
            float4 v = *(const float4*)(qr + 4*u);
            int d = lseg + 4*u;
            Qs[(d+0)*68 + lrow] = v.x;
            Qs[(d+1)*68 + lrow] = v.y;
            Qs[(d+2)*68 + lrow] = v.z;
            Qs[(d+3)*68 + lrow] = v.w;
        }
        if (tid < 64) Qms[tid] = Qm[(size_t)b*NQ + q0 + tid];
    }

    float oacc[4][4] = {};
    float rsum = 0.f;
    const float scale = 0.044194173824159216f;   // 1/sqrt(512)

    for (int kt = 0; kt < NQ/64; kt++) {
        __syncthreads();
        const int k0 = kt * 64;
        const float* kr = Kp + base + (size_t)(k0 + lrow) * D_ + lseg;
        const float* vr = Vp + base + (size_t)(k0 + lrow) * D_ + lseg;
        #pragma unroll
        for (int u = 0; u < 4; u++) {
            float4 v = *(const float4*)(kr + 4*u);
            int d = lseg + 4*u;
            Ks[(d+0)*68 + lrow] = v.x;
            Ks[(d+1)*68 + lrow] = v.y;
            Ks[(d+2)*68 + lrow] = v.z;
            Ks[(d+3)*68 + lrow] = v.w;
            *(float4*)&Vs[lrow*64 + lseg + 4*u] = *(const float4*)(vr + 4*u);
        }
        if (tid < 64) Kms[tid] = Km[(size_t)b*NQ + k0 + tid];
        __syncthreads();

        float sacc[4][4] = {};
        #pragma unroll 16
        for (int d = 0; d < 64; d++) {
            float4 a  = *(const float4*)&Qs[d*68 + (ty<<2)];
            float4 bb = *(const float4*)&Ks[d*68 + (tx<<2)];
            float ar[4] = {a.x, a.y, a.z, a.w};
            float br[4] = {bb.x, bb.y, bb.z, bb.w};
            #pragma unroll
            for (int i = 0; i < 4; i++)
                #pragma unroll
                for (int j = 0; j < 4; j++)
                    sacc[i][j] += ar[i] * br[j];
        }

        float qmv[4], kmv[4];
        #pragma unroll
        for (int i = 0; i < 4; i++) qmv[i] = Qms[(ty<<2)+i];
        #pragma unroll
        for (int j = 0; j < 4; j++) kmv[j] = Kms[(tx<<2)+j];
        #pragma unroll
        for (int i = 0; i < 4; i++)
            #pragma unroll
            for (int j = 0; j < 4; j++) {
                float s = sacc[i][j] * scale;
                float x = __expf(__expf(s) * kmv[j]) * qmv[i];
                Xs[((tx<<2)+j)*68 + (ty<<2)+i] = x;
            }
        __syncthreads();

        if (tid < 64) {
            float s = 0.f;
            #pragma unroll 8
            for (int k = 0; k < 64; k++) s += Xs[k*68 + tid];
            rsum += s;
        }

        #pragma unroll 16
        for (int k = 0; k < 64; k++) {
            float4 x = *(const float4*)&Xs[k*68 + (ty<<2)];
            float4 v = *(const float4*)&Vs[k*64 + (tx<<2)];
            float xr[4]  = {x.x, x.y, x.z, x.w};
            float vr4[4] = {v.x, v.y, v.z, v.w};
            #pragma unroll
            for (int i = 0; i < 4; i++)
                #pragma unroll
                for (int j = 0; j < 4; j++)
                    oacc[i][j] += xr[i] * vr4[j];
        }
    }

    __syncthreads();
    if (tid < 64) Rs[tid] = rsum + 1e-8f;
    __syncthreads();

    #pragma unroll
    for (int i = 0; i < 4; i++) {
        int q = (ty<<2) + i;
        float inv = 1.f / Rs[q];
        float4 o;
        o.x = Qs[((tx<<2)+0)*68 + q] + oacc[i][0]*inv;
        o.y = Qs[((tx<<2)+1)*68 + q] + oacc[i][1]*inv;
        o.z = Qs[((tx<<2)+2)*68 + q] + oacc[i][2]*inv;
        o.w = Qs[((tx<<2)+3)*68 + q] + oacc[i][3]*inv;
        *(float4*)&O[base + (size_t)(q0+q)*D_ + (tx<<2)] = o;
    }
}

__global__ void __launch_bounds__(128) ln_k(
    const float* __restrict__ X, const float* __restrict__ g,
    const float* __restrict__ bb, float* __restrict__ Y)
{
    const int row = blockIdx.x;
    const int t = threadIdx.x;
    const float4 v = *(const float4*)(X + (size_t)row*D_ + 4*t);
    float s  = v.x + v.y + v.z + v.w;
    float s2 = v.x*v.x + v.y*v.y + v.z*v.z + v.w*v.w;
    #pragma unroll
    for (int o = 16; o > 0; o >>= 1) {
        s  += __shfl_xor_sync(0xffffffffu, s,  o);
        s2 += __shfl_xor_sync(0xffffffffu, s2, o);
    }
    __shared__ float ws[4], ws2[4];
    if ((t & 31) == 0) { ws[t>>5] = s; ws2[t>>5] = s2; }
    __syncthreads();
    s  = ws[0]  + ws[1]  + ws[2]  + ws[3];
    s2 = ws2[0] + ws2[1] + ws2[2] + ws2[3];
    const float mean = s * (1.f/D_);
    const float var  = s2 * (1.f/D_) - mean*mean;
    const float inv  = rsqrtf(var + 1e-5f);
    const float4 gv = *(const float4*)(g  + 4*t);
    const float4 bv = *(const float4*)(bb + 4*t);
    float4 o;
    o.x = (v.x - mean)*inv*gv.x + bv.x;
    o.y = (v.y - mean)*inv*gv.y + bv.y;
    o.z = (v.z - mean)*inv*gv.z + bv.z;
    o.w = (v.w - mean)*inv*gv.w + bv.w;
    *(float4*)(Y + (size_t)row*D_ + 4*t) = o;
}

extern "C" void kernel_launch(void* const* d_in, const int* in_sizes, int n_in,
                              void* d_out, int out_size)
{
    const float* Q  = (const float*)d_in[0];
    const float* K  = (const float*)d_in[1];
    const float* Qm = (const float*)d_in[2];
    const float* Km = (const float*)d_in[3];
    const float* Wq = (const float*)d_in[4];
    const float* bq = (const float*)d_in[5];
    const float* Wk = (const float*)d_in[6];
    const float* bk = (const float*)d_in[7];
    const float* Wv = (const float*)d_in[8];
    const float* bv = (const float*)d_in[9];
    const float* Wo = (const float*)d_in[10];
    const float* bo = (const float*)d_in[11];
    const float* g0 = (const float*)d_in[12];
    const float* b0 = (const float*)d_in[13];
    const float* g1 = (const float*)d_in[14];
    const float* b1 = (const float*)d_in[15];
    float* out = (float*)d_out;

    float *pQp, *pKp, *pV, *pO1, *pO2;
    cudaGetSymbolAddress((void**)&pQp, g_Qp);
    cudaGetSymbolAddress((void**)&pKp, g_Kp);
    cudaGetSymbolAddress((void**)&pV,  g_V);
    cudaGetSymbolAddress((void**)&pO1, g_O1);
    cudaGetSymbolAddress((void**)&pO2, g_O2);

    cudaFuncSetAttribute(attn_k, cudaFuncAttributeMaxDynamicSharedMemorySize, ATT_SMEM);

    dim3 gblk(256);
    dim3 ggrid(D_/BN, M_/BM);

    gemm_k<0><<<ggrid, gblk>>>(Q, Wq, bq, Qm, pQp, M_, D_, D_);
    gemm_k<0><<<ggrid, gblk>>>(K, Wk, bk, Km, pKp, M_, D_, D_);
    gemm_k<1><<<ggrid, gblk>>>(K, Wv, bv, nullptr, pV, M_, D_, D_);

    dim3 agrid(NQ/64, B_, H_);
    attn_k<<<agrid, 256, ATT_SMEM>>>(pQp, pKp, pV, Qm, Km, pO1);

    ln_k<<<M_, 128>>>(pO1, g0, b0, pO2);
    gemm_k<2><<<ggrid, gblk>>>(pO2, Wo, bo, nullptr, pQp, M_, D_, D_);
    ln_k<<<M_, 128>>>(pQp, g1, b1, out);
}

// round 2
// speedup vs baseline: 1.4226x; 1.4226x over previous
#include <cuda_runtime.h>
#include <math.h>

#define B_  16
#define NQ  1024
#define D_  512
#define H_  8
#define DH  64
#define M_  (B_*NQ)

__device__ float g_Qp[(size_t)M_*D_];
__device__ float g_Kp[(size_t)M_*D_];
__device__ float g_V [(size_t)M_*D_];
__device__ float g_O1[(size_t)M_*D_];
__device__ float g_O2[(size_t)M_*D_];

// ================= TF32 tensor-core GEMM =================
// C[M,N] = epi(A[M,K] @ W[K,N]);  block 128x128, 8 warps (4m x 2n), warp 32x64
#define TBM 128
#define TBN 128
#define TBK 16
#define ASTRIDE 20    // [m][k] padded: frag banks (20*r + c) % 32 all distinct
#define BSTRIDE 136   // [k][n] padded: frag banks (8*k + n) % 32 all distinct

__device__ __forceinline__ unsigned f2tf32(float x) {
    unsigned u;
    asm("cvt.rna.tf32.f32 %0, %1;" : "=r"(u) : "f"(x));
    return u;
}

template<int EPI>   // 0: (acc+bias)*mask[row]   1: acc+bias   2: A[row,col]+relu(acc+bias)
__global__ void __launch_bounds__(256) gemm_tc(
    const float* __restrict__ A, const float* __restrict__ W,
    const float* __restrict__ bias, const float* __restrict__ mask,
    float* __restrict__ C, int M, int N, int K)
{
    __shared__ unsigned As[2][TBM][ASTRIDE];
    __shared__ unsigned Bs[2][TBK][BSTRIDE];

    const int tid  = threadIdx.x;
    const int lane = tid & 31;
    const int wid  = tid >> 5;
    const int warp_m = (wid >> 1) * 32;
    const int warp_n = (wid & 1) * 64;
    const int bm = blockIdx.y * TBM;
    const int bn = blockIdx.x * TBN;

    // global load mappings (coalesced)
    const int arow = tid >> 2;            // 0..63 (+64 for second)
    const int acol = (tid & 3) * 4;       // 0,4,8,12
    const int brow = tid >> 4;            // 0..15
    const int bcol = (tid & 15) * 4;      // 0..60 (+64 for second)

    const float* Ap = A + (size_t)(bm + arow) * K + acol;
    const float* Wp = W + (size_t)brow * N + bn + bcol;

    float acc[2][8][4];
    #pragma unroll
    for (int mt = 0; mt < 2; mt++)
        #pragma unroll
        for (int nt = 0; nt < 8; nt++)
            #pragma unroll
            for (int c = 0; c < 4; c++) acc[mt][nt][c] = 0.f;

    float4 ar0, ar1, br0, br1;
    ar0 = *(const float4*)(Ap);
    ar1 = *(const float4*)(Ap + (size_t)64 * K);
    br0 = *(const float4*)(Wp);
    br1 = *(const float4*)(Wp + 64);

    // store tile 0
    {
        unsigned* a0 = &As[0][arow][acol];
        a0[0]=f2tf32(ar0.x); a0[1]=f2tf32(ar0.y); a0[2]=f2tf32(ar0.z); a0[3]=f2tf32(ar0.w);
        unsigned* a1 = &As[0][arow+64][acol];
        a1[0]=f2tf32(ar1.x); a1[1]=f2tf32(ar1.y); a1[2]=f2tf32(ar1.z); a1[3]=f2tf32(ar1.w);
        unsigned* b0 = &Bs[0][brow][bcol];
        b0[0]=f2tf32(br0.x); b0[1]=f2tf32(br0.y); b0[2]=f2tf32(br0.z); b0[3]=f2tf32(br0.w);
        unsigned* b1 = &Bs[0][brow][bcol+64];
        b1[0]=f2tf32(br1.x); b1[1]=f2tf32(br1.y); b1[2]=f2tf32(br1.z); b1[3]=f2tf32(br1.w);
    }
    __syncthreads();

    const int NT = K / TBK;   // 32
    const int gr = lane >> 2, gc = lane & 3;

    for (int t = 0; t < NT; t++) {
        const int buf = t & 1;
        if (t + 1 < NT) {
            const int k0 = (t + 1) * TBK;
            ar0 = *(const float4*)(Ap + k0);
            ar1 = *(const float4*)(Ap + (size_t)64 * K + k0);
            br0 = *(const float4*)(Wp + (size_t)k0 * N);
            br1 = *(const float4*)(Wp + (size_t)k0 * N + 64);
        }

        #pragma unroll
        for (int ks = 0; ks < 2; ks++) {
            const int k0 = ks * 8;
            unsigned af[2][4], bf[8][2];
            #pragma unroll
            for (int mt = 0; mt < 2; mt++) {
                const int r = warp_m + mt * 16 + gr;
                af[mt][0] = As[buf][r    ][k0 + gc];
                af[mt][1] = As[buf][r + 8][k0 + gc];
                af[mt][2] = As[buf][r    ][k0 + gc + 4];
                af[mt][3] = As[buf][r + 8][k0 + gc + 4];
            }
            #pragma unroll
            for (int nt = 0; nt < 8; nt++) {
                const int c = warp_n + nt * 8 + gr;
                bf[nt][0] = Bs[buf][k0 + gc    ][c];
                bf[nt][1] = Bs[buf][k0 + gc + 4][c];
            }
            #pragma unroll
            for (int mt = 0; mt < 2; mt++)
                #pragma unroll
                for (int nt = 0; nt < 8; nt++) {
                    asm volatile(
                        "mma.sync.aligned.m16n8k8.row.col.f32.tf32.tf32.f32 "
                        "{%0,%1,%2,%3}, {%4,%5,%6,%7}, {%8,%9}, {%0,%1,%2,%3};"
                        : "+f"(acc[mt][nt][0]), "+f"(acc[mt][nt][1]),
                          "+f"(acc[mt][nt][2]), "+f"(acc[mt][nt][3])
                        : "r"(af[mt][0]), "r"(af[mt][1]), "r"(af[mt][2]), "r"(af[mt][3]),
                          "r"(bf[nt][0]), "r"(bf[nt][1]));
                }
        }

        if (t + 1 < NT) {
            const int nb = (t + 1) & 1;
            unsigned* a0 = &As[nb][arow][acol];
            a0[0]=f2tf32(ar0.x); a0[1]=f2tf32(ar0.y); a0[2]=f2tf32(ar0.z); a0[3]=f2tf32(ar0.w);
            unsigned* a1 = &As[nb][arow+64][acol];
            a1[0]=f2tf32(ar1.x); a1[1]=f2tf32(ar1.y); a1[2]=f2tf32(ar1.z); a1[3]=f2tf32(ar1.w);
            unsigned* b0 = &Bs[nb][brow][bcol];
            b0[0]=f2tf32(br0.x); b0[1]=f2tf32(br0.y); b0[2]=f2tf32(br0.z); b0[3]=f2tf32(br0.w);
            unsigned* b1 = &Bs[nb][brow][bcol+64];
            b1[0]=f2tf32(br1.x); b1[1]=f2tf32(br1.y); b1[2]=f2tf32(br1.z); b1[3]=f2tf32(br1.w);
            __syncthreads();
        }
    }

    // epilogue
    #pragma unroll
    for (int mt = 0; mt < 2; mt++) {
        #pragma unroll
        for (int nt = 0; nt < 8; nt++) {
            const int row0 = bm + warp_m + mt * 16 + gr;
            const int row1 = row0 + 8;
            const int col  = bn + warp_n + nt * 8 + gc * 2;
            const float b0 = bias[col], b1 = bias[col + 1];
            float v0 = acc[mt][nt][0] + b0;
            float v1 = acc[mt][nt][1] + b1;
            float v2 = acc[mt][nt][2] + b0;
            float v3 = acc[mt][nt][3] + b1;
            if (EPI == 0) {
                const float m0 = mask[row0], m1 = mask[row1];
                v0 *= m0; v1 *= m0; v2 *= m1; v3 *= m1;
            } else if (EPI == 2) {
                const float2 r0 = *(const float2*)(A + (size_t)row0 * K + col);
                const float2 r1 = *(const float2*)(A + (size_t)row1 * K + col);
                v0 = r0.x + fmaxf(v0, 0.f);
                v1 = r0.y + fmaxf(v1, 0.f);
                v2 = r1.x + fmaxf(v2, 0.f);
                v3 = r1.y + fmaxf(v3, 0.f);
            }
            *(float2*)&C[(size_t)row0 * N + col] = make_float2(v0, v1);
            *(float2*)&C[(size_t)row1 * N + col] = make_float2(v2, v3);
        }
    }
}

// ================= attention (unchanged fp32) =================
#define ATT_SMEM ((3*64*68 + 64*64 + 3*64) * 4)

__global__ void __launch_bounds__(256) attn_k(
    const float* __restrict__ Qp, const float* __restrict__ Kp,
    const float* __restrict__ Vp, const float* __restrict__ Qm,
    const float* __restrict__ Km, float* __restrict__ O)
{
    extern __shared__ float sm[];
    float* Qs  = sm;             // [64][68] (d, q)
    float* Ks  = Qs + 64*68;     // [64][68] (d, k)
    float* Xs  = Ks + 64*68;     // [64][68] (k, q)
    float* Vs  = Xs + 64*68;     // [64][64] (k, d)
    float* Qms = Vs + 64*64;
    float* Kms = Qms + 64;
    float* Rs  = Kms + 64;

    const int tid = threadIdx.x;
    const int tx = tid & 15, ty = tid >> 4;
    const int q0 = blockIdx.x * 64;
    const int b  = blockIdx.y;
    const int h  = blockIdx.z;
    const size_t base = (size_t)b * NQ * D_ + (size_t)h * DH;

    const int lrow = tid >> 2;
    const int lseg = (tid & 3) << 4;

    {
        const float* qr = Qp + base + (size_t)(q0 + lrow) * D_ + lseg;
        #pragma unroll
        for (int u = 0; u < 4; u++) {
            float4 v = *(const float4*)(qr + 4*u);
            int d = lseg + 4*u;
            Qs[(d+0)*68 + lrow] = v.x;
            Qs[(d+1)*68 + lrow] = v.y;
            Qs[(d+2)*68 + lrow] = v.z;
            Qs[(d+3)*68 + lrow] = v.w;
        }
        if (tid < 64) Qms[tid] = Qm[(size_t)b*NQ + q0 + tid];
    }

    float oacc[4][4] = {};
    float rsum = 0.f;
    const float scale = 0.044194173824159216f;

    for (int kt = 0; kt < NQ/64; kt++) {
        __syncthreads();
        const int k0 = kt * 64;
        const float* kr = Kp + base + (size_t)(k0 + lrow) * D_ + lseg;
        const float* vr = Vp + base + (size_t)(k0 + lrow) * D_ + lseg;
        #pragma unroll
        for (int u = 0; u < 4; u++) {
            float4 v = *(const float4*)(kr + 4*u);
            int d = lseg + 4*u;
            Ks[(d+0)*68 + lrow] = v.x;
            Ks[(d+1)*68 + lrow] = v.y;
            Ks[(d+2)*68 + lrow] = v.z;
            Ks[(d+3)*68 + lrow] = v.w;
            *(float4*)&Vs[lrow*64 + lseg + 4*u] = *(const float4*)(vr + 4*u);
        }
        if (tid < 64) Kms[tid] = Km[(size_t)b*NQ + k0 + tid];
        __syncthreads();

        float sacc[4][4] = {};
        #pragma unroll 16
        for (int d = 0; d < 64; d++) {
            float4 a  = *(const float4*)&Qs[d*68 + (ty<<2)];
            float4 bb = *(const float4*)&Ks[d*68 + (tx<<2)];
            float ar[4] = {a.x, a.y, a.z, a.w};
            float br[4] = {bb.x, bb.y, bb.z, bb.w};
            #pragma unroll
            for (int i = 0; i < 4; i++)
                #pragma unroll
                for (int j = 0; j < 4; j++)
                    sacc[i][j] += ar[i] * br[j];
        }

        float qmv[4], kmv[4];
        #pragma unroll
        for (int i = 0; i < 4; i++) qmv[i] = Qms[(ty<<2)+i];
        #pragma unroll
        for (int j = 0; j < 4; j++) kmv[j] = Kms[(tx<<2)+j];
        #pragma unroll
        for (int i = 0; i < 4; i++)
            #pragma unroll
            for (int j = 0; j < 4; j++) {
                float s = sacc[i][j] * scale;
                float x = __expf(__expf(s) * kmv[j]) * qmv[i];
                Xs[((tx<<2)+j)*68 + (ty<<2)+i] = x;
            }
        __syncthreads();

        if (tid < 64) {
            float s = 0.f;
            #pragma unroll 8
            for (int k = 0; k < 64; k++) s += Xs[k*68 + tid];
            rsum += s;
        }

        #pragma unroll 16
        for (int k = 0; k < 64; k++) {
            float4 x = *(const float4*)&Xs[k*68 + (ty<<2)];
            float4 v = *(const float4*)&Vs[k*64 + (tx<<2)];
            float xr[4]  = {x.x, x.y, x.z, x.w};
            float vr4[4] = {v.x, v.y, v.z, v.w};
            #pragma unroll
            for (int i = 0; i < 4; i++)
                #pragma unroll
                for (int j = 0; j < 4; j++)
                    oacc[i][j] += xr[i] * vr4[j];
        }
    }

    __syncthreads();
    if (tid < 64) Rs[tid] = rsum + 1e-8f;
    __syncthreads();

    #pragma unroll
    for (int i = 0; i < 4; i++) {
        int q = (ty<<2) + i;
        float inv = 1.f / Rs[q];
        float4 o;
        o.x = Qs[((tx<<2)+0)*68 + q] + oacc[i][0]*inv;
        o.y = Qs[((tx<<2)+1)*68 + q] + oacc[i][1]*inv;
        o.z = Qs[((tx<<2)+2)*68 + q] + oacc[i][2]*inv;
        o.w = Qs[((tx<<2)+3)*68 + q] + oacc[i][3]*inv;
        *(float4*)&O[base + (size_t)(q0+q)*D_ + (tx<<2)] = o;
    }
}

// ================= LayerNorm =================
__global__ void __launch_bounds__(128) ln_k(
    const float* __restrict__ X, const float* __restrict__ g,
    const float* __restrict__ bb, float* __restrict__ Y)
{
    const int row = blockIdx.x;
    const int t = threadIdx.x;
    const float4 v = *(const float4*)(X + (size_t)row*D_ + 4*t);
    float s  = v.x + v.y + v.z + v.w;
    float s2 = v.x*v.x + v.y*v.y + v.z*v.z + v.w*v.w;
    #pragma unroll
    for (int o = 16; o > 0; o >>= 1) {
        s  += __shfl_xor_sync(0xffffffffu, s,  o);
        s2 += __shfl_xor_sync(0xffffffffu, s2, o);
    }
    __shared__ float ws[4], ws2[4];
    if ((t & 31) == 0) { ws[t>>5] = s; ws2[t>>5] = s2; }
    __syncthreads();
    s  = ws[0]  + ws[1]  + ws[2]  + ws[3];
    s2 = ws2[0] + ws2[1] + ws2[2] + ws2[3];
    const float mean = s * (1.f/D_);
    const float var  = s2 * (1.f/D_) - mean*mean;
    const float inv  = rsqrtf(var + 1e-5f);
    const float4 gv = *(const float4*)(g  + 4*t);
    const float4 bv = *(const float4*)(bb + 4*t);
    float4 o;
    o.x = (v.x - mean)*inv*gv.x + bv.x;
    o.y = (v.y - mean)*inv*gv.y + bv.y;
    o.z = (v.z - mean)*inv*gv.z + bv.z;
    o.w = (v.w - mean)*inv*gv.w + bv.w;
    *(float4*)(Y + (size_t)row*D_ + 4*t) = o;
}

extern "C" void kernel_launch(void* const* d_in, const int* in_sizes, int n_in,
                              void* d_out, int out_size)
{
    const float* Q  = (const float*)d_in[0];
    const float* K  = (const float*)d_in[1];
    const float* Qm = (const float*)d_in[2];
    const float* Km = (const float*)d_in[3];
    const float* Wq = (const float*)d_in[4];
    const float* bq = (const float*)d_in[5];
    const float* Wk = (const float*)d_in[6];
    const float* bk = (const float*)d_in[7];
    const float* Wv = (const float*)d_in[8];
    const float* bv = (const float*)d_in[9];
    const float* Wo = (const float*)d_in[10];
    const float* bo = (const float*)d_in[11];
    const float* g0 = (const float*)d_in[12];
    const float* b0 = (const float*)d_in[13];
    const float* g1 = (const float*)d_in[14];
    const float* b1 = (const float*)d_in[15];
    float* out = (float*)d_out;

    float *pQp, *pKp, *pV, *pO1, *pO2;
    cudaGetSymbolAddress((void**)&pQp, g_Qp);
    cudaGetSymbolAddress((void**)&pKp, g_Kp);
    cudaGetSymbolAddress((void**)&pV,  g_V);
    cudaGetSymbolAddress((void**)&pO1, g_O1);
    cudaGetSymbolAddress((void**)&pO2, g_O2);

    cudaFuncSetAttribute(attn_k, cudaFuncAttributeMaxDynamicSharedMemorySize, ATT_SMEM);

    dim3 gblk(256);
    dim3 ggrid(D_/TBN, M_/TBM);   // (4, 128)

    gemm_tc<0><<<ggrid, gblk>>>(Q, Wq, bq, Qm, pQp, M_, D_, D_);
    gemm_tc<0><<<ggrid, gblk>>>(K, Wk, bk, Km, pKp, M_, D_, D_);
    gemm_tc<1><<<ggrid, gblk>>>(K, Wv, bv, nullptr, pV, M_, D_, D_);

    dim3 agrid(NQ/64, B_, H_);
    attn_k<<<agrid, 256, ATT_SMEM>>>(pQp, pKp, pV, Qm, Km, pO1);

    ln_k<<<M_, 128>>>(pO1, g0, b0, pO2);
    gemm_tc<2><<<ggrid, gblk>>>(pO2, Wo, bo, nullptr, pQp, M_, D_, D_);
    ln_k<<<M_, 128>>>(pQp, g1, b1, out);
}

// round 3
// speedup vs baseline: 2.9316x; 2.0608x over previous
#include <cuda_runtime.h>
#include <math.h>

#define B_  16
#define NQ  1024
#define D_  512
#define H_  8
#define DH  64
#define M_  (B_*NQ)

__device__ float g_Qp[(size_t)M_*D_];
__device__ float g_Kp[(size_t)M_*D_];
__device__ float g_V [(size_t)M_*D_];
__device__ float g_O1[(size_t)M_*D_];
__device__ float g_O2[(size_t)M_*D_];

__device__ __forceinline__ unsigned f2tf32(float x) {
    unsigned u;
    asm("cvt.rna.tf32.f32 %0, %1;" : "=r"(u) : "f"(x));
    return u;
}
__device__ __forceinline__ float tf32f(float x) { return __uint_as_float(f2tf32(x)); }

#define MMA_TF32(acc, a0,a1,a2,a3, b0,b1) \
    asm volatile("mma.sync.aligned.m16n8k8.row.col.f32.tf32.tf32.f32 " \
        "{%0,%1,%2,%3}, {%4,%5,%6,%7}, {%8,%9}, {%0,%1,%2,%3};" \
        : "+f"(acc[0]), "+f"(acc[1]), "+f"(acc[2]), "+f"(acc[3]) \
        : "r"(a0), "r"(a1), "r"(a2), "r"(a3), "r"(b0), "r"(b1))

// ================= TF32 tensor-core GEMM (unchanged from R1) =================
#define TBM 128
#define TBN 128
#define TBK 16
#define ASTRIDE 20
#define BSTRIDE 136

template<int EPI>   // 0: (acc+bias)*mask[row]   1: acc+bias   2: A+relu(acc+bias)
__global__ void __launch_bounds__(256) gemm_tc(
    const float* __restrict__ A, const float* __restrict__ W,
    const float* __restrict__ bias, const float* __restrict__ mask,
    float* __restrict__ C, int M, int N, int K)
{
    __shared__ unsigned As[2][TBM][ASTRIDE];
    __shared__ unsigned Bs[2][TBK][BSTRIDE];

    const int tid  = threadIdx.x;
    const int lane = tid & 31;
    const int wid  = tid >> 5;
    const int warp_m = (wid >> 1) * 32;
    const int warp_n = (wid & 1) * 64;
    const int bm = blockIdx.y * TBM;
    const int bn = blockIdx.x * TBN;

    const int arow = tid >> 2;
    const int acol = (tid & 3) * 4;
    const int brow = tid >> 4;
    const int bcol = (tid & 15) * 4;

    const float* Ap = A + (size_t)(bm + arow) * K + acol;
    const float* Wp = W + (size_t)brow * N + bn + bcol;

    float acc[2][8][4];
    #pragma unroll
    for (int mt = 0; mt < 2; mt++)
        #pragma unroll
        for (int nt = 0; nt < 8; nt++)
            #pragma unroll
            for (int c = 0; c < 4; c++) acc[mt][nt][c] = 0.f;

    float4 ar0, ar1, br0, br1;
    ar0 = *(const float4*)(Ap);
    ar1 = *(const float4*)(Ap + (size_t)64 * K);
    br0 = *(const float4*)(Wp);
    br1 = *(const float4*)(Wp + 64);

    {
        unsigned* a0 = &As[0][arow][acol];
        a0[0]=f2tf32(ar0.x); a0[1]=f2tf32(ar0.y); a0[2]=f2tf32(ar0.z); a0[3]=f2tf32(ar0.w);
        unsigned* a1 = &As[0][arow+64][acol];
        a1[0]=f2tf32(ar1.x); a1[1]=f2tf32(ar1.y); a1[2]=f2tf32(ar1.z); a1[3]=f2tf32(ar1.w);
        unsigned* b0 = &Bs[0][brow][bcol];
        b0[0]=f2tf32(br0.x); b0[1]=f2tf32(br0.y); b0[2]=f2tf32(br0.z); b0[3]=f2tf32(br0.w);
        unsigned* b1 = &Bs[0][brow][bcol+64];
        b1[0]=f2tf32(br1.x); b1[1]=f2tf32(br1.y); b1[2]=f2tf32(br1.z); b1[3]=f2tf32(br1.w);
    }
    __syncthreads();

    const int NT = K / TBK;
    const int gr = lane >> 2, gc = lane & 3;

    for (int t = 0; t < NT; t++) {
        const int buf = t & 1;
        if (t + 1 < NT) {
            const int k0 = (t + 1) * TBK;
            ar0 = *(const float4*)(Ap + k0);
            ar1 = *(const float4*)(Ap + (size_t)64 * K + k0);
            br0 = *(const float4*)(Wp + (size_t)k0 * N);
            br1 = *(const float4*)(Wp + (size_t)k0 * N + 64);
        }

        #pragma unroll
        for (int ks = 0; ks < 2; ks++) {
            const int k0 = ks * 8;
            unsigned af[2][4], bf[8][2];
            #pragma unroll
            for (int mt = 0; mt < 2; mt++) {
                const int r = warp_m + mt * 16 + gr;
                af[mt][0] = As[buf][r    ][k0 + gc];
                af[mt][1] = As[buf][r + 8][k0 + gc];
                af[mt][2] = As[buf][r    ][k0 + gc + 4];
                af[mt][3] = As[buf][r + 8][k0 + gc + 4];
            }
            #pragma unroll
            for (int nt = 0; nt < 8; nt++) {
                const int c = warp_n + nt * 8 + gr;
                bf[nt][0] = Bs[buf][k0 + gc    ][c];
                bf[nt][1] = Bs[buf][k0 + gc + 4][c];
            }
            #pragma unroll
            for (int mt = 0; mt < 2; mt++)
                #pragma unroll
                for (int nt = 0; nt < 8; nt++)
                    MMA_TF32(acc[mt][nt], af[mt][0], af[mt][1], af[mt][2], af[mt][3],
                             bf[nt][0], bf[nt][1]);
        }

        if (t + 1 < NT) {
            const int nb = (t + 1) & 1;
            unsigned* a0 = &As[nb][arow][acol];
            a0[0]=f2tf32(ar0.x); a0[1]=f2tf32(ar0.y); a0[2]=f2tf32(ar0.z); a0[3]=f2tf32(ar0.w);
            unsigned* a1 = &As[nb][arow+64][acol];
            a1[0]=f2tf32(ar1.x); a1[1]=f2tf32(ar1.y); a1[2]=f2tf32(ar1.z); a1[3]=f2tf32(ar1.w);
            unsigned* b0 = &Bs[nb][brow][bcol];
            b0[0]=f2tf32(br0.x); b0[1]=f2tf32(br0.y); b0[2]=f2tf32(br0.z); b0[3]=f2tf32(br0.w);
            unsigned* b1 = &Bs[nb][brow][bcol+64];
            b1[0]=f2tf32(br1.x); b1[1]=f2tf32(br1.y); b1[2]=f2tf32(br1.z); b1[3]=f2tf32(br1.w);
            __syncthreads();
        }
    }

    #pragma unroll
    for (int mt = 0; mt < 2; mt++) {
        #pragma unroll
        for (int nt = 0; nt < 8; nt++) {
            const int row0 = bm + warp_m + mt * 16 + gr;
            const int row1 = row0 + 8;
            const int col  = bn + warp_n + nt * 8 + gc * 2;
            const float b0 = bias[col], b1 = bias[col + 1];
            float v0 = acc[mt][nt][0] + b0;
            float v1 = acc[mt][nt][1] + b1;
            float v2 = acc[mt][nt][2] + b0;
            float v3 = acc[mt][nt][3] + b1;
            if (EPI == 0) {
                const float m0 = mask[row0], m1 = mask[row1];
                v0 *= m0; v1 *= m0; v2 *= m1; v3 *= m1;
            } else if (EPI == 2) {
                const float2 r0 = *(const float2*)(A + (size_t)row0 * K + col);
                const float2 r1 = *(const float2*)(A + (size_t)row1 * K + col);
                v0 = r0.x + fmaxf(v0, 0.f);
                v1 = r0.y + fmaxf(v1, 0.f);
                v2 = r1.x + fmaxf(v2, 0.f);
                v3 = r1.y + fmaxf(v3, 0.f);
            }
            *(float2*)&C[(size_t)row0 * N + col] = make_float2(v0, v1);
            *(float2*)&C[(size_t)row1 * N + col] = make_float2(v2, v3);
        }
    }
}

// ================= TF32 tensor-core attention =================
// block: 128 queries x one (b,h). 8 warps 4m x 2n (warp 32x32). 16 key tiles of 64.
#define SQ 68   // Qs stride  (== 4 mod 32)
#define SK 68   // Ks stride  (== 4 mod 32)
#define SV 72   // Vs stride  (== 8 mod 32)
#define SX 68   // Xs stride  (== 4 mod 32)
#define ATT_SMEM ((128*SQ + 64*SK + 64*SV + 128*SX + 128 + 64 + 128) * 4)

__global__ void __launch_bounds__(256) attn_tc(
    const float* __restrict__ Qp, const float* __restrict__ Kp,
    const float* __restrict__ Vp, const float* __restrict__ Qm,
    const float* __restrict__ Km, float* __restrict__ O)
{
    extern __shared__ float smf[];
    float* Qs  = smf;               // [128][SQ]  q-major
    float* Ks  = Qs  + 128*SQ;      // [64][SK]   key-major
    float* Vs  = Ks  + 64*SK;       // [64][SV]   key-major
    float* Xs  = Vs  + 64*SV;       // [128][SX]  q-major
    float* qms = Xs  + 128*SX;      // [128]
    float* kms = qms + 128;         // [64]
    float* rs  = kms + 64;          // [128]

    const int tid  = threadIdx.x;
    const int lane = tid & 31;
    const int wid  = tid >> 5;
    const int gr = lane >> 2, gc = lane & 3;
    const int warp_m = (wid >> 1) * 32;
    const int warp_n = (wid & 1) * 32;

    const int q0 = blockIdx.x * 128;
    const int b  = blockIdx.y;
    const int h  = blockIdx.z;
    const size_t base = (size_t)b * NQ * D_ + (size_t)h * DH;
    const float scale = 0.044194173824159216f;   // 1/sqrt(512)

    // ---- load Q tile (tf32) + Qm, zero rowsums ----
    {
        const int r  = tid >> 1;
        const int ch = (tid & 1) * 32;
        const float* qp = Qp + base + (size_t)(q0 + r) * D_ + ch;
        #pragma unroll
        for (int u = 0; u < 8; u++) {
            float4 v = *(const float4*)(qp + 4*u);
            float* d = &Qs[r*SQ + ch + 4*u];
            d[0]=tf32f(v.x); d[1]=tf32f(v.y); d[2]=tf32f(v.z); d[3]=tf32f(v.w);
        }
        if (tid < 128) { qms[tid] = Qm[(size_t)b*NQ + q0 + tid]; rs[tid] = 0.f; }
    }

    // ---- K/V prefetch mapping: 16 floats/thread each ----
    const int krow = tid >> 2;
    const int kc   = (tid & 3) * 16;
    float4 krg[4], vrg[4];
    {
        const float* kp = Kp + base + (size_t)krow * D_ + kc;
        const float* vp = Vp + base + (size_t)krow * D_ + kc;
        #pragma unroll
        for (int u = 0; u < 4; u++) {
            krg[u] = *(const float4*)(kp + 4*u);
            vrg[u] = *(const float4*)(vp + 4*u);
        }
    }

    float oacc[2][4][4];
    #pragma unroll
    for (int mt = 0; mt < 2; mt++)
        #pragma unroll
        for (int nt = 0; nt < 4; nt++)
            #pragma unroll
            for (int c = 0; c < 4; c++) oacc[mt][nt][c] = 0.f;

    for (int kt = 0; kt < NQ/64; kt++) {
        __syncthreads();   // prev AV reads of Vs/Xs done; safe to overwrite
        // store prefetched K/V (tf32)
        #pragma unroll
        for (int u = 0; u < 4; u++) {
            float* dk = &Ks[krow*SK + kc + 4*u];
            dk[0]=tf32f(krg[u].x); dk[1]=tf32f(krg[u].y); dk[2]=tf32f(krg[u].z); dk[3]=tf32f(krg[u].w);
            float* dv = &Vs[krow*SV + kc + 4*u];
            dv[0]=tf32f(vrg[u].x); dv[1]=tf32f(vrg[u].y); dv[2]=tf32f(vrg[u].z); dv[3]=tf32f(vrg[u].w);
        }
        if (tid < 64) kms[tid] = Km[(size_t)b*NQ + kt*64 + tid];
        __syncthreads();

        // prefetch next K tile
        if (kt + 1 < NQ/64) {
            const float* kp = Kp + base + (size_t)((kt+1)*64 + krow) * D_ + kc;
            #pragma unroll
            for (int u = 0; u < 4; u++) krg[u] = *(const float4*)(kp + 4*u);
        }

        // ---- S = Q . K^T   (A = Qs[q][d], B = K[key][d] natural) ----
        float sacc[2][4][4];
        #pragma unroll
        for (int mt = 0; mt < 2; mt++)
            #pragma unroll
            for (int nt = 0; nt < 4; nt++)
                #pragma unroll
                for (int c = 0; c < 4; c++) sacc[mt][nt][c] = 0.f;

        #pragma unroll
        for (int ks = 0; ks < 8; ks++) {
            const int k0 = ks * 8;
            unsigned af[2][4], bf[4][2];
            #pragma unroll
            for (int mt = 0; mt < 2; mt++) {
                const int r = warp_m + mt*16 + gr;
                af[mt][0] = __float_as_uint(Qs[r*SQ       + k0 + gc]);
                af[mt][1] = __float_as_uint(Qs[(r+8)*SQ   + k0 + gc]);
                af[mt][2] = __float_as_uint(Qs[r*SQ       + k0 + gc + 4]);
                af[mt][3] = __float_as_uint(Qs[(r+8)*SQ   + k0 + gc + 4]);
            }
            #pragma unroll
            for (int nt = 0; nt < 4; nt++) {
                const int key = warp_n + nt*8 + gr;
                bf[nt][0] = __float_as_uint(Ks[key*SK + k0 + gc]);
                bf[nt][1] = __float_as_uint(Ks[key*SK + k0 + gc + 4]);
            }
            #pragma unroll
            for (int mt = 0; mt < 2; mt++)
                #pragma unroll
                for (int nt = 0; nt < 4; nt++)
                    MMA_TF32(sacc[mt][nt], af[mt][0], af[mt][1], af[mt][2], af[mt][3],
                             bf[nt][0], bf[nt][1]);
        }

        // prefetch next V tile
        if (kt + 1 < NQ/64) {
            const float* vp = Vp + base + (size_t)((kt+1)*64 + krow) * D_ + kc;
            #pragma unroll
            for (int u = 0; u < 4; u++) vrg[u] = *(const float4*)(vp + 4*u);
        }

        // ---- double-exp transform, rowsums, X -> smem (tf32) ----
        #pragma unroll
        for (int mt = 0; mt < 2; mt++) {
            const int r0 = warp_m + mt*16 + gr;
            const float qm0 = qms[r0], qm1 = qms[r0 + 8];
            float p0 = 0.f, p1 = 0.f;
            #pragma unroll
            for (int nt = 0; nt < 4; nt++) {
                const int col = warp_n + nt*8 + gc*2;
                const float km0 = kms[col], km1 = kms[col + 1];
                float x00 = __expf(__expf(sacc[mt][nt][0]*scale) * km0) * qm0;
                float x01 = __expf(__expf(sacc[mt][nt][1]*scale) * km1) * qm0;
                float x10 = __expf(__expf(sacc[mt][nt][2]*scale) * km0) * qm1;
                float x11 = __expf(__expf(sacc[mt][nt][3]*scale) * km1) * qm1;
                x00 = tf32f(x00); x01 = tf32f(x01); x10 = tf32f(x10); x11 = tf32f(x11);
                p0 += x00 + x01;
                p1 += x10 + x11;
                *(float2*)&Xs[r0*SX + col]     = make_float2(x00, x01);
                *(float2*)&Xs[(r0+8)*SX + col] = make_float2(x10, x11);
            }
            // reduce over gc (4 lanes of a group)
            p0 += __shfl_xor_sync(0xffffffffu, p0, 1);
            p0 += __shfl_xor_sync(0xffffffffu, p0, 2);
            p1 += __shfl_xor_sync(0xffffffffu, p1, 1);
            p1 += __shfl_xor_sync(0xffffffffu, p1, 2);
            if (gc == 0) {
                atomicAdd(&rs[r0],     p0);
                atomicAdd(&rs[r0 + 8], p1);
            }
        }
        __syncthreads();

        // ---- O += X . V   (A = Xs[q][key], B = V[key][d] natural) ----
        #pragma unroll
        for (int ks = 0; ks < 8; ks++) {
            const int k0 = ks * 8;
            unsigned af[2][4], bf[4][2];
            #pragma unroll
            for (int mt = 0; mt < 2; mt++) {
                const int r = warp_m + mt*16 + gr;
                af[mt][0] = __float_as_uint(Xs[r*SX     + k0 + gc]);
                af[mt][1] = __float_as_uint(Xs[(r+8)*SX + k0 + gc]);
                af[mt][2] = __float_as_uint(Xs[r*SX     + k0 + gc + 4]);
                af[mt][3] = __float_as_uint(Xs[(r+8)*SX + k0 + gc + 4]);
            }
            #pragma unroll
            for (int nt = 0; nt < 4; nt++) {
                const int c = warp_n + nt*8 + gr;
                bf[nt][0] = __float_as_uint(Vs[(k0 + gc)*SV     + c]);
                bf[nt][1] = __float_as_uint(Vs[(k0 + gc + 4)*SV + c]);
            }
            #pragma unroll
            for (int mt = 0; mt < 2; mt++)
                #pragma unroll
                for (int nt = 0; nt < 4; nt++)
                    MMA_TF32(oacc[mt][nt], af[mt][0], af[mt][1], af[mt][2], af[mt][3],
                             bf[nt][0], bf[nt][1]);
        }
    }

    __syncthreads();

    // ---- epilogue: O = Qp + oacc / (rowsum + 1e-8) ----
    #pragma unroll
    for (int mt = 0; mt < 2; mt++) {
        const int r0 = warp_m + mt*16 + gr;
        const float inv0 = 1.f / (rs[r0]     + 1e-8f);
        const float inv1 = 1.f / (rs[r0 + 8] + 1e-8f);
        #pragma unroll
        for (int nt = 0; nt < 4; nt++) {
            const int col = warp_n + nt*8 + gc*2;
            const float2 q0v = *(const float2*)(Qp + base + (size_t)(q0 + r0)*D_ + col);
            const float2 q1v = *(const float2*)(Qp + base + (size_t)(q0 + r0 + 8)*D_ + col);
            float2 o0 = make_float2(q0v.x + oacc[mt][nt][0]*inv0,
                                    q0v.y + oacc[mt][nt][1]*inv0);
            float2 o1 = make_float2(q1v.x + oacc[mt][nt][2]*inv1,
                                    q1v.y + oacc[mt][nt][3]*inv1);
            *(float2*)&O[base + (size_t)(q0 + r0)*D_ + col]     = o0;
            *(float2*)&O[base + (size_t)(q0 + r0 + 8)*D_ + col] = o1;
        }
    }
}

// ================= LayerNorm =================
__global__ void __launch_bounds__(128) ln_k(
    const float* __restrict__ X, const float* __restrict__ g,
    const float* __restrict__ bb, float* __restrict__ Y)
{
    const int row = blockIdx.x;
    const int t = threadIdx.x;
    const float4 v = *(const float4*)(X + (size_t)row*D_ + 4*t);
    float s  = v.x + v.y + v.z + v.w;
    float s2 = v.x*v.x + v.y*v.y + v.z*v.z + v.w*v.w;
    #pragma unroll
    for (int o = 16; o > 0; o >>= 1) {
        s  += __shfl_xor_sync(0xffffffffu, s,  o);
        s2 += __shfl_xor_sync(0xffffffffu, s2, o);
    }
    __shared__ float ws[4], ws2[4];
    if ((t & 31) == 0) { ws[t>>5] = s; ws2[t>>5] = s2; }
    __syncthreads();
    s  = ws[0]  + ws[1]  + ws[2]  + ws[3];
    s2 = ws2[0] + ws2[1] + ws2[2] + ws2[3];
    const float mean = s * (1.f/D_);
    const float var  = s2 * (1.f/D_) - mean*mean;
    const float inv  = rsqrtf(var + 1e-5f);
    const float4 gv = *(const float4*)(g  + 4*t);
    const float4 bv = *(const float4*)(bb + 4*t);
    float4 o;
    o.x = (v.x - mean)*inv*gv.x + bv.x;
    o.y = (v.y - mean)*inv*gv.y + bv.y;
    o.z = (v.z - mean)*inv*gv.z + bv.z;
    o.w = (v.w - mean)*inv*gv.w + bv.w;
    *(float4*)(Y + (size_t)row*D_ + 4*t) = o;
}

extern "C" void kernel_launch(void* const* d_in, const int* in_sizes, int n_in,
                              void* d_out, int out_size)
{
    const float* Q  = (const float*)d_in[0];
    const float* K  = (const float*)d_in[1];
    const float* Qm = (const float*)d_in[2];
    const float* Km = (const float*)d_in[3];
    const float* Wq = (const float*)d_in[4];
    const float* bq = (const float*)d_in[5];
    const float* Wk = (const float*)d_in[6];
    const float* bk = (const float*)d_in[7];
    const float* Wv = (const float*)d_in[8];
    const float* bv = (const float*)d_in[9];
    const float* Wo = (const float*)d_in[10];
    const float* bo = (const float*)d_in[11];
    const float* g0 = (const float*)d_in[12];
    const float* b0 = (const float*)d_in[13];
    const float* g1 = (const float*)d_in[14];
    const float* b1 = (const float*)d_in[15];
    float* out = (float*)d_out;

    float *pQp, *pKp, *pV, *pO1, *pO2;
    cudaGetSymbolAddress((void**)&pQp, g_Qp);
    cudaGetSymbolAddress((void**)&pKp, g_Kp);
    cudaGetSymbolAddress((void**)&pV,  g_V);
    cudaGetSymbolAddress((void**)&pO1, g_O1);
    cudaGetSymbolAddress((void**)&pO2, g_O2);

    cudaFuncSetAttribute(attn_tc, cudaFuncAttributeMaxDynamicSharedMemorySize, ATT_SMEM);

    dim3 gblk(256);
    dim3 ggrid(D_/TBN, M_/TBM);

    gemm_tc<0><<<ggrid, gblk>>>(Q, Wq, bq, Qm, pQp, M_, D_, D_);
    gemm_tc<0><<<ggrid, gblk>>>(K, Wk, bk, Km, pKp, M_, D_, D_);
    gemm_tc<1><<<ggrid, gblk>>>(K, Wv, bv, nullptr, pV, M_, D_, D_);

    dim3 agrid(NQ/128, B_, H_);   // 8 x 16 x 8 = 1024 blocks
    attn_tc<<<agrid, 256, ATT_SMEM>>>(pQp, pKp, pV, Qm, Km, pO1);

    ln_k<<<M_, 128>>>(pO1, g0, b0, pO2);
    gemm_tc<2><<<ggrid, gblk>>>(pO2, Wo, bo, nullptr, pQp, M_, D_, D_);
    ln_k<<<M_, 128>>>(pQp, g1, b1, out);
}

// round 4
// speedup vs baseline: 3.8606x; 1.3169x over previous
#include <cuda_runtime.h>
#include <cuda_bf16.h>
#include <math.h>
#include <stdint.h>

#define B_  16
#define NQ  1024
#define D_  512
#define H_  8
#define DH  64
#define M_  (B_*NQ)

__device__ float g_Qp[(size_t)M_*D_];
__device__ float g_Kp[(size_t)M_*D_];
__device__ float g_V [(size_t)M_*D_];
__device__ float g_O1[(size_t)M_*D_];
__device__ float g_O2[(size_t)M_*D_];

__device__ __forceinline__ unsigned f2tf32(float x) {
    unsigned u;
    asm("cvt.rna.tf32.f32 %0, %1;" : "=r"(u) : "f"(x));
    return u;
}

__device__ __forceinline__ unsigned pkbf(float lo, float hi) {
    unsigned r;
    asm("cvt.rn.bf16x2.f32 %0, %1, %2;" : "=r"(r) : "f"(hi), "f"(lo));
    return r;
}

__device__ __forceinline__ uint32_t sptr(const void* p) {
    return (uint32_t)__cvta_generic_to_shared(p);
}

#define MMA_TF32(acc, a0,a1,a2,a3, b0,b1) \
    asm volatile("mma.sync.aligned.m16n8k8.row.col.f32.tf32.tf32.f32 " \
        "{%0,%1,%2,%3}, {%4,%5,%6,%7}, {%8,%9}, {%0,%1,%2,%3};" \
        : "+f"(acc[0]), "+f"(acc[1]), "+f"(acc[2]), "+f"(acc[3]) \
        : "r"(a0), "r"(a1), "r"(a2), "r"(a3), "r"(b0), "r"(b1))

#define MMA_BF16(acc, a, b0, b1) \
    asm volatile("mma.sync.aligned.m16n8k16.row.col.f32.bf16.bf16.f32 " \
        "{%0,%1,%2,%3}, {%4,%5,%6,%7}, {%8,%9}, {%0,%1,%2,%3};" \
        : "+f"(acc[0]), "+f"(acc[1]), "+f"(acc[2]), "+f"(acc[3]) \
        : "r"(a[0]), "r"(a[1]), "r"(a[2]), "r"(a[3]), "r"(b0), "r"(b1))

#define LDSM4(r, addr) \
    asm volatile("ldmatrix.sync.aligned.m8n8.x4.shared.b16 {%0,%1,%2,%3}, [%4];" \
        : "=r"(r[0]), "=r"(r[1]), "=r"(r[2]), "=r"(r[3]) : "r"(addr))

#define LDSM4T(r, addr) \
    asm volatile("ldmatrix.sync.aligned.m8n8.x4.trans.shared.b16 {%0,%1,%2,%3}, [%4];" \
        : "=r"(r[0]), "=r"(r[1]), "=r"(r[2]), "=r"(r[3]) : "r"(addr))

// ================= TF32 tensor-core GEMM (unchanged) =================
#define TBM 128
#define TBN 128
#define TBK 16
#define ASTRIDE 20
#define BSTRIDE 136

template<int EPI>   // 0: (acc+bias)*mask[row]   1: acc+bias   2: A+relu(acc+bias)
__global__ void __launch_bounds__(256) gemm_tc(
    const float* __restrict__ A, const float* __restrict__ W,
    const float* __restrict__ bias, const float* __restrict__ mask,
    float* __restrict__ C, int M, int N, int K)
{
    __shared__ unsigned As[2][TBM][ASTRIDE];
    __shared__ unsigned Bs[2][TBK][BSTRIDE];

    const int tid  = threadIdx.x;
    const int lane = tid & 31;
    const int wid  = tid >> 5;
    const int warp_m = (wid >> 1) * 32;
    const int warp_n = (wid & 1) * 64;
    const int bm = blockIdx.y * TBM;
    const int bn = blockIdx.x * TBN;

    const int arow = tid >> 2;
    const int acol = (tid & 3) * 4;
    const int brow = tid >> 4;
    const int bcol = (tid & 15) * 4;

    const float* Ap = A + (size_t)(bm + arow) * K + acol;
    const float* Wp = W + (size_t)brow * N + bn + bcol;

    float acc[2][8][4];
    #pragma unroll
    for (int mt = 0; mt < 2; mt++)
        #pragma unroll
        for (int nt = 0; nt < 8; nt++)
            #pragma unroll
            for (int c = 0; c < 4; c++) acc[mt][nt][c] = 0.f;

    float4 ar0, ar1, br0, br1;
    ar0 = *(const float4*)(Ap);
    ar1 = *(const float4*)(Ap + (size_t)64 * K);
    br0 = *(const float4*)(Wp);
    br1 = *(const float4*)(Wp + 64);

    {
        unsigned* a0 = &As[0][arow][acol];
        a0[0]=f2tf32(ar0.x); a0[1]=f2tf32(ar0.y); a0[2]=f2tf32(ar0.z); a0[3]=f2tf32(ar0.w);
        unsigned* a1 = &As[0][arow+64][acol];
        a1[0]=f2tf32(ar1.x); a1[1]=f2tf32(ar1.y); a1[2]=f2tf32(ar1.z); a1[3]=f2tf32(ar1.w);
        unsigned* b0 = &Bs[0][brow][bcol];
        b0[0]=f2tf32(br0.x); b0[1]=f2tf32(br0.y); b0[2]=f2tf32(br0.z); b0[3]=f2tf32(br0.w);
        unsigned* b1 = &Bs[0][brow][bcol+64];
        b1[0]=f2tf32(br1.x); b1[1]=f2tf32(br1.y); b1[2]=f2tf32(br1.z); b1[3]=f2tf32(br1.w);
    }
    __syncthreads();

    const int NT = K / TBK;
    const int gr = lane >> 2, gc = lane & 3;

    for (int t = 0; t < NT; t++) {
        const int buf = t & 1;
        if (t + 1 < NT) {
            const int k0 = (t + 1) * TBK;
            ar0 = *(const float4*)(Ap + k0);
            ar1 = *(const float4*)(Ap + (size_t)64 * K + k0);
            br0 = *(const float4*)(Wp + (size_t)k0 * N);
            br1 = *(const float4*)(Wp + (size_t)k0 * N + 64);
        }

        #pragma unroll
        for (int ks = 0; ks < 2; ks++) {
            const int k0 = ks * 8;
            unsigned af[2][4], bf[8][2];
            #pragma unroll
            for (int mt = 0; mt < 2; mt++) {
                const int r = warp_m + mt * 16 + gr;
                af[mt][0] = As[buf][r    ][k0 + gc];
                af[mt][1] = As[buf][r + 8][k0 + gc];
                af[mt][2] = As[buf][r    ][k0 + gc + 4];
                af[mt][3] = As[buf][r + 8][k0 + gc + 4];
            }
            #pragma unroll
            for (int nt = 0; nt < 8; nt++) {
                const int c = warp_n + nt * 8 + gr;
                bf[nt][0] = Bs[buf][k0 + gc    ][c];
                bf[nt][1] = Bs[buf][k0 + gc + 4][c];
            }
            #pragma unroll
            for (int mt = 0; mt < 2; mt++)
                #pragma unroll
                for (int nt = 0; nt < 8; nt++)
                    MMA_TF32(acc[mt][nt], af[mt][0], af[mt][1], af[mt][2], af[mt][3],
                             bf[nt][0], bf[nt][1]);
        }

        if (t + 1 < NT) {
            const int nb = (t + 1) & 1;
            unsigned* a0 = &As[nb][arow][acol];
            a0[0]=f2tf32(ar0.x); a0[1]=f2tf32(ar0.y); a0[2]=f2tf32(ar0.z); a0[3]=f2tf32(ar0.w);
            unsigned* a1 = &As[nb][arow+64][acol];
            a1[0]=f2tf32(ar1.x); a1[1]=f2tf32(ar1.y); a1[2]=f2tf32(ar1.z); a1[3]=f2tf32(ar1.w);
            unsigned* b0 = &Bs[nb][brow][bcol];
            b0[0]=f2tf32(br0.x); b0[1]=f2tf32(br0.y); b0[2]=f2tf32(br0.z); b0[3]=f2tf32(br0.w);
            unsigned* b1 = &Bs[nb][brow][bcol+64];
            b1[0]=f2tf32(br1.x); b1[1]=f2tf32(br1.y); b1[2]=f2tf32(br1.z); b1[3]=f2tf32(br1.w);
            __syncthreads();
        }
    }

    #pragma unroll
    for (int mt = 0; mt < 2; mt++) {
        #pragma unroll
        for (int nt = 0; nt < 8; nt++) {
            const int row0 = bm + warp_m + mt * 16 + gr;
            const int row1 = row0 + 8;
            const int col  = bn + warp_n + nt * 8 + gc * 2;
            const float b0 = bias[col], b1 = bias[col + 1];
            float v0 = acc[mt][nt][0] + b0;
            float v1 = acc[mt][nt][1] + b1;
            float v2 = acc[mt][nt][2] + b0;
            float v3 = acc[mt][nt][3] + b1;
            if (EPI == 0) {
                const float m0 = mask[row0], m1 = mask[row1];
                v0 *= m0; v1 *= m0; v2 *= m1; v3 *= m1;
            } else if (EPI == 2) {
                const float2 r0 = *(const float2*)(A + (size_t)row0 * K + col);
                const float2 r1 = *(const float2*)(A + (size_t)row1 * K + col);
                v0 = r0.x + fmaxf(v0, 0.f);
                v1 = r0.y + fmaxf(v1, 0.f);
                v2 = r1.x + fmaxf(v2, 0.f);
                v3 = r1.y + fmaxf(v3, 0.f);
            }
            *(float2*)&C[(size_t)row0 * N + col] = make_float2(v0, v1);
            *(float2*)&C[(size_t)row1 * N + col] = make_float2(v2, v3);
        }
    }
}

// ================= bf16 tensor-core attention =================
// block: 128 q x one (b,h); key tile 64; 8 warps 4m x 2n (warp 32x32).
// smem tiles bf16, row stride 72 halves (=144B, 36 words == 4 mod 32:
// ldmatrix phases and STS.64 stores provably bank-conflict-free).
#define SH  72
#define SHW 36
#define ATT_SMEM (( (128+64+64+128)*SH )*2 + (128+64+128)*4)

__global__ void __launch_bounds__(256, 2) attn_bf(
    const float* __restrict__ Qp, const float* __restrict__ Kp,
    const float* __restrict__ Vp, const float* __restrict__ Qm,
    const float* __restrict__ Km, float* __restrict__ O)
{
    extern __shared__ char smc[];
    __nv_bfloat16* Qs = (__nv_bfloat16*)smc;       // [128][SH]
    __nv_bfloat16* Ks = Qs + 128*SH;               // [64][SH]
    __nv_bfloat16* Vs = Ks + 64*SH;                // [64][SH]
    __nv_bfloat16* Xs = Vs + 64*SH;                // [128][SH]
    float* qms = (float*)(Xs + 128*SH);            // [128]
    float* kms = qms + 128;                        // [64]
    float* rs  = kms + 64;                         // [128]

    const int tid  = threadIdx.x;
    const int lane = tid & 31;
    const int wid  = tid >> 5;
    const int gr = lane >> 2, gc = lane & 3;
    const int warp_m = (wid >> 1) * 32;
    const int warp_n = (wid & 1) * 32;

    const int q0 = blockIdx.x * 128;
    const int b  = blockIdx.y;
    const int h  = blockIdx.z;
    const size_t base = (size_t)b * NQ * D_ + (size_t)h * DH;
    const float scale = 0.044194173824159216f;   // 1/sqrt(512)

    const int lrow = tid >> 4;          // 0..15
    const int lc4  = (tid & 15) * 4;    // 0..60

    // ---- Q tile -> bf16 smem (coalesced LDG.128, conflict-free STS.64) ----
    #pragma unroll
    for (int p = 0; p < 8; p++) {
        const int row = p * 16 + lrow;
        float4 v = *(const float4*)(Qp + base + (size_t)(q0 + row) * D_ + lc4);
        *(uint2*)&Qs[row*SH + lc4] = make_uint2(pkbf(v.x, v.y), pkbf(v.z, v.w));
    }
    if (tid < 128) { qms[tid] = Qm[(size_t)b*NQ + q0 + tid]; rs[tid] = 0.f; }

    // ---- prefetch K/V tile 0 ----
    float4 kpre[4], vpre[4];
    #pragma unroll
    for (int p = 0; p < 4; p++) {
        const int row = p * 16 + lrow;
        kpre[p] = *(const float4*)(Kp + base + (size_t)row * D_ + lc4);
        vpre[p] = *(const float4*)(Vp + base + (size_t)row * D_ + lc4);
    }

    float oacc[2][4][4];
    #pragma unroll
    for (int mt = 0; mt < 2; mt++)
        #pragma unroll
        for (int nt = 0; nt < 4; nt++)
            #pragma unroll
            for (int c = 0; c < 4; c++) oacc[mt][nt][c] = 0.f;

    // ldmatrix lane address components (computed once)
    const int l7  = lane & 7;
    const int l8  = (lane & 8) ? 8 : 0;
    const int l16 = (lane & 16) ? 8 : 0;

    for (int kt = 0; kt < NQ/64; kt++) {
        __syncthreads();
        // store prefetched K/V as bf16
        #pragma unroll
        for (int p = 0; p < 4; p++) {
            const int row = p * 16 + lrow;
            *(uint2*)&Ks[row*SH + lc4] = make_uint2(pkbf(kpre[p].x, kpre[p].y),
                                                    pkbf(kpre[p].z, kpre[p].w));
            *(uint2*)&Vs[row*SH + lc4] = make_uint2(pkbf(vpre[p].x, vpre[p].y),
                                                    pkbf(vpre[p].z, vpre[p].w));
        }
        if (tid < 64) kms[tid] = Km[(size_t)b*NQ + kt*64 + tid];
        __syncthreads();

        // prefetch next K
        if (kt + 1 < NQ/64) {
            #pragma unroll
            for (int p = 0; p < 4; p++) {
                const int row = p * 16 + lrow;
                kpre[p] = *(const float4*)(Kp + base + (size_t)((kt+1)*64 + row) * D_ + lc4);
            }
        }

        // ---- S = Q.K^T ----
        float sacc[2][4][4];
        #pragma unroll
        for (int mt = 0; mt < 2; mt++)
            #pragma unroll
            for (int nt = 0; nt < 4; nt++)
                #pragma unroll
                for (int c = 0; c < 4; c++) sacc[mt][nt][c] = 0.f;

        #pragma unroll
        for (int ks = 0; ks < 4; ks++) {
            unsigned af[2][4], bq[2][4];
            #pragma unroll
            for (int mt = 0; mt < 2; mt++) {
                const int r = warp_m + mt*16 + l7 + l8;
                const int c = ks*16 + l16;
                LDSM4(af[mt], sptr(&Qs[r*SH + c]));
            }
            #pragma unroll
            for (int ntp = 0; ntp < 2; ntp++) {
                const int r = warp_n + ntp*16 + l7 + l16;
                const int c = ks*16 + l8;
                LDSM4(bq[ntp], sptr(&Ks[r*SH + c]));
            }
            #pragma unroll
            for (int mt = 0; mt < 2; mt++)
                #pragma unroll
                for (int nt = 0; nt < 4; nt++) {
                    const unsigned b0 = bq[nt>>1][(nt&1)*2];
                    const unsigned b1 = bq[nt>>1][(nt&1)*2+1];
                    MMA_BF16(sacc[mt][nt], af[mt], b0, b1);
                }
        }

        // prefetch next V
        if (kt + 1 < NQ/64) {
            #pragma unroll
            for (int p = 0; p < 4; p++) {
                const int row = p * 16 + lrow;
                vpre[p] = *(const float4*)(Vp + base + (size_t)((kt+1)*64 + row) * D_ + lc4);
            }
        }

        // ---- double-exp transform, rowsums, X -> bf16 smem ----
        unsigned* Xw = (unsigned*)Xs;
        #pragma unroll
        for (int mt = 0; mt < 2; mt++) {
            const int r0 = warp_m + mt*16 + gr;
            const float qm0 = qms[r0], qm1 = qms[r0 + 8];
            float p0 = 0.f, p1 = 0.f;
            #pragma unroll
            for (int nt = 0; nt < 4; nt++) {
                const int col = warp_n + nt*8 + gc*2;
                const float km0 = kms[col], km1 = kms[col + 1];
                float x00 = __expf(__expf(sacc[mt][nt][0]*scale) * km0) * qm0;
                float x01 = __expf(__expf(sacc[mt][nt][1]*scale) * km1) * qm0;
                float x10 = __expf(__expf(sacc[mt][nt][2]*scale) * km0) * qm1;
                float x11 = __expf(__expf(sacc[mt][nt][3]*scale) * km1) * qm1;
                p0 += x00 + x01;
                p1 += x10 + x11;
                const int wcol = (warp_n >> 1) + nt*4 + gc;
                Xw[r0*SHW + wcol]     = pkbf(x00, x01);
                Xw[(r0+8)*SHW + wcol] = pkbf(x10, x11);
            }
            p0 += __shfl_xor_sync(0xffffffffu, p0, 1);
            p0 += __shfl_xor_sync(0xffffffffu, p0, 2);
            p1 += __shfl_xor_sync(0xffffffffu, p1, 1);
            p1 += __shfl_xor_sync(0xffffffffu, p1, 2);
            if (gc == 0) {
                atomicAdd(&rs[r0],     p0);
                atomicAdd(&rs[r0 + 8], p1);
            }
        }
        __syncthreads();

        // ---- O += X.V ----
        #pragma unroll
        for (int ks = 0; ks < 4; ks++) {
            unsigned af[2][4], bv[2][4];
            #pragma unroll
            for (int mt = 0; mt < 2; mt++) {
                const int r = warp_m + mt*16 + l7 + l8;
                const int c = ks*16 + l16;
                LDSM4(af[mt], sptr(&Xs[r*SH + c]));
            }
            #pragma unroll
            for (int ntp = 0; ntp < 2; ntp++) {
                const int r = ks*16 + l7 + l8;          // key rows
                const int c = warp_n + ntp*16 + l16;    // d cols
                LDSM4T(bv[ntp], sptr(&Vs[r*SH + c]));
            }
            #pragma unroll
            for (int mt = 0; mt < 2; mt++)
                #pragma unroll
                for (int nt = 0; nt < 4; nt++) {
                    const unsigned b0 = bv[nt>>1][(nt&1)*2];
                    const unsigned b1 = bv[nt>>1][(nt&1)*2+1];
                    MMA_BF16(oacc[mt][nt], af[mt], b0, b1);
                }
        }
    }

    __syncthreads();

    // ---- epilogue: O = Qp + oacc / (rowsum + 1e-8) ----
    #pragma unroll
    for (int mt = 0; mt < 2; mt++) {
        const int r0 = warp_m + mt*16 + gr;
        const float inv0 = 1.f / (rs[r0]     + 1e-8f);
        const float inv1 = 1.f / (rs[r0 + 8] + 1e-8f);
        #pragma unroll
        for (int nt = 0; nt < 4; nt++) {
            const int col = warp_n + nt*8 + gc*2;
            const float2 q0v = *(const float2*)(Qp + base + (size_t)(q0 + r0)*D_ + col);
            const float2 q1v = *(const float2*)(Qp + base + (size_t)(q0 + r0 + 8)*D_ + col);
            float2 o0 = make_float2(q0v.x + oacc[mt][nt][0]*inv0,
                                    q0v.y + oacc[mt][nt][1]*inv0);
            float2 o1 = make_float2(q1v.x + oacc[mt][nt][2]*inv1,
                                    q1v.y + oacc[mt][nt][3]*inv1);
            *(float2*)&O[base + (size_t)(q0 + r0)*D_ + col]     = o0;
            *(float2*)&O[base + (size_t)(q0 + r0 + 8)*D_ + col] = o1;
        }
    }
}

// ================= LayerNorm =================
__global__ void __launch_bounds__(128) ln_k(
    const float* __restrict__ X, const float* __restrict__ g,
    const float* __restrict__ bb, float* __restrict__ Y)
{
    const int row = blockIdx.x;
    const int t = threadIdx.x;
    const float4 v = *(const float4*)(X + (size_t)row*D_ + 4*t);
    float s  = v.x + v.y + v.z + v.w;
    float s2 = v.x*v.x + v.y*v.y + v.z*v.z + v.w*v.w;
    #pragma unroll
    for (int o = 16; o > 0; o >>= 1) {
        s  += __shfl_xor_sync(0xffffffffu, s,  o);
        s2 += __shfl_xor_sync(0xffffffffu, s2, o);
    }
    __shared__ float ws[4], ws2[4];
    if ((t & 31) == 0) { ws[t>>5] = s; ws2[t>>5] = s2; }
    __syncthreads();
    s  = ws[0]  + ws[1]  + ws[2]  + ws[3];
    s2 = ws2[0] + ws2[1] + ws2[2] + ws2[3];
    const float mean = s * (1.f/D_);
    const float var  = s2 * (1.f/D_) - mean*mean;
    const float inv  = rsqrtf(var + 1e-5f);
    const float4 gv = *(const float4*)(g  + 4*t);
    const float4 bv = *(const float4*)(bb + 4*t);
    float4 o;
    o.x = (v.x - mean)*inv*gv.x + bv.x;
    o.y = (v.y - mean)*inv*gv.y + bv.y;
    o.z = (v.z - mean)*inv*gv.z + bv.z;
    o.w = (v.w - mean)*inv*gv.w + bv.w;
    *(float4*)(Y + (size_t)row*D_ + 4*t) = o;
}

extern "C" void kernel_launch(void* const* d_in, const int* in_sizes, int n_in,
                              void* d_out, int out_size)
{
    const float* Q  = (const float*)d_in[0];
    const float* K  = (const float*)d_in[1];
    const float* Qm = (const float*)d_in[2];
    const float* Km = (const float*)d_in[3];
    const float* Wq = (const float*)d_in[4];
    const float* bq = (const float*)d_in[5];
    const float* Wk = (const float*)d_in[6];
    const float* bk = (const float*)d_in[7];
    const float* Wv = (const float*)d_in[8];
    const float* bv = (const float*)d_in[9];
    const float* Wo = (const float*)d_in[10];
    const float* bo = (const float*)d_in[11];
    const float* g0 = (const float*)d_in[12];
    const float* b0 = (const float*)d_in[13];
    const float* g1 = (const float*)d_in[14];
    const float* b1 = (const float*)d_in[15];
    float* out = (float*)d_out;

    float *pQp, *pKp, *pV, *pO1, *pO2;
    cudaGetSymbolAddress((void**)&pQp, g_Qp);
    cudaGetSymbolAddress((void**)&pKp, g_Kp);
    cudaGetSymbolAddress((void**)&pV,  g_V);
    cudaGetSymbolAddress((void**)&pO1, g_O1);
    cudaGetSymbolAddress((void**)&pO2, g_O2);

    cudaFuncSetAttribute(attn_bf, cudaFuncAttributeMaxDynamicSharedMemorySize, ATT_SMEM);

    dim3 gblk(256);
    dim3 ggrid(D_/TBN, M_/TBM);

    gemm_tc<0><<<ggrid, gblk>>>(Q, Wq, bq, Qm, pQp, M_, D_, D_);
    gemm_tc<0><<<ggrid, gblk>>>(K, Wk, bk, Km, pKp, M_, D_, D_);
    gemm_tc<1><<<ggrid, gblk>>>(K, Wv, bv, nullptr, pV, M_, D_, D_);

    dim3 agrid(NQ/128, B_, H_);
    attn_bf<<<agrid, 256, ATT_SMEM>>>(pQp, pKp, pV, Qm, Km, pO1);

    ln_k<<<M_, 128>>>(pO1, g0, b0, pO2);
    gemm_tc<2><<<ggrid, gblk>>>(pO2, Wo, bo, nullptr, pQp, M_, D_, D_);
    ln_k<<<M_, 128>>>(pQp, g1, b1, out);
}

// round 5
// speedup vs baseline: 4.2575x; 1.1028x over previous
#include <cuda_runtime.h>
#include <cuda_bf16.h>
#include <math.h>
#include <stdint.h>

#define B_  16
#define NQ  1024
#define D_  512
#define H_  8
#define DH  64
#define M_  (B_*NQ)

__device__ float g_Qp[(size_t)M_*D_];
__device__ float g_Kp[(size_t)M_*D_];
__device__ float g_V [(size_t)M_*D_];
__device__ float g_O1[(size_t)M_*D_];
__device__ float g_O2[(size_t)M_*D_];

__device__ __forceinline__ unsigned f2tf32(float x) {
    unsigned u;
    asm("cvt.rna.tf32.f32 %0, %1;" : "=r"(u) : "f"(x));
    return u;
}
__device__ __forceinline__ unsigned pkbf(float lo, float hi) {
    unsigned r;
    asm("cvt.rn.bf16x2.f32 %0, %1, %2;" : "=r"(r) : "f"(hi), "f"(lo));
    return r;
}
__device__ __forceinline__ uint32_t sptr(const void* p) {
    return (uint32_t)__cvta_generic_to_shared(p);
}

#define MMA_TF32(acc, a0,a1,a2,a3, b0,b1) \
    asm volatile("mma.sync.aligned.m16n8k8.row.col.f32.tf32.tf32.f32 " \
        "{%0,%1,%2,%3}, {%4,%5,%6,%7}, {%8,%9}, {%0,%1,%2,%3};" \
        : "+f"(acc[0]), "+f"(acc[1]), "+f"(acc[2]), "+f"(acc[3]) \
        : "r"(a0), "r"(a1), "r"(a2), "r"(a3), "r"(b0), "r"(b1))

#define MMA_BF16(acc, a, b0, b1) \
    asm volatile("mma.sync.aligned.m16n8k16.row.col.f32.bf16.bf16.f32 " \
        "{%0,%1,%2,%3}, {%4,%5,%6,%7}, {%8,%9}, {%0,%1,%2,%3};" \
        : "+f"(acc[0]), "+f"(acc[1]), "+f"(acc[2]), "+f"(acc[3]) \
        : "r"(a[0]), "r"(a[1]), "r"(a[2]), "r"(a[3]), "r"(b0), "r"(b1))

#define LDSM4(r, addr) \
    asm volatile("ldmatrix.sync.aligned.m8n8.x4.shared.b16 {%0,%1,%2,%3}, [%4];" \
        : "=r"(r[0]), "=r"(r[1]), "=r"(r[2]), "=r"(r[3]) : "r"(addr))

#define LDSM4T(r, addr) \
    asm volatile("ldmatrix.sync.aligned.m8n8.x4.trans.shared.b16 {%0,%1,%2,%3}, [%4];" \
        : "=r"(r[0]), "=r"(r[1]), "=r"(r[2]), "=r"(r[3]) : "r"(addr))

// ================= TF32 GEMM with ldmatrix feeds =================
// block 128x128, 8 warps (4m x 2n), warp 32x64, BK=16 double-buffered.
// As [m][k] pad 20; Bs [n][k] pad 20 (n-major so B frags come from plain ldmatrix).
#define TBM 128
#define TBN 128
#define TBK 16
#define GST 20

template<int EPI>   // 0: (acc+bias)*mask[row]   1: acc+bias   2: A+relu(acc+bias)
__global__ void __launch_bounds__(256, 2) gemm_tc(
    const float* __restrict__ A, const float* __restrict__ W,
    const float* __restrict__ bias, const float* __restrict__ mask,
    float* __restrict__ C, int M, int N, int K)
{
    __shared__ unsigned As[2][TBM][GST];
    __shared__ unsigned Bs[2][TBN][GST];

    const int tid  = threadIdx.x;
    const int lane = tid & 31;
    const int wid  = tid >> 5;
    const int warp_m = (wid >> 1) * 32;
    const int warp_n = (wid & 1) * 64;
    const int bm = blockIdx.y * TBM;
    const int bn = blockIdx.x * TBN;
    const int gr = lane >> 2, gc = lane & 3;
    const int l7 = lane & 7;
    const int a_l8  = (lane & 8)  ? 8 : 0;
    const int a_l16 = (lane & 16) ? 4 : 0;
    const int b_l8  = (lane & 8)  ? 4 : 0;
    const int b_l16 = (lane & 16) ? 8 : 0;

    // A loads: thread covers rows (arow, arow+64), 4 consecutive k
    const int arow = tid >> 2;
    const int acol = (tid & 3) * 4;
    const float* Ap = A + (size_t)(bm + arow) * K + acol;

    // B loads: thread covers column n, k-quads (kq2, kq2+2)
    const int bnl  = tid & 127;
    const int kq2  = tid >> 7;
    const float* Wp = W + bn + bnl;

    float acc[2][8][4];
    #pragma unroll
    for (int mt = 0; mt < 2; mt++)
        #pragma unroll
        for (int nt = 0; nt < 8; nt++)
            #pragma unroll
            for (int c = 0; c < 4; c++) acc[mt][nt][c] = 0.f;

    float4 ar0, ar1;
    float bpre[2][4];

    // prefetch tile 0
    ar0 = *(const float4*)(Ap);
    ar1 = *(const float4*)(Ap + (size_t)64 * K);
    #pragma unroll
    for (int it = 0; it < 2; it++) {
        const int k = (kq2 + 2*it) * 4;
        #pragma unroll
        for (int j = 0; j < 4; j++)
            bpre[it][j] = Wp[(size_t)(k + j) * N];
    }
    // store tile 0
    {
        *(uint4*)&As[0][arow][acol] =
            make_uint4(f2tf32(ar0.x), f2tf32(ar0.y), f2tf32(ar0.z), f2tf32(ar0.w));
        *(uint4*)&As[0][arow+64][acol] =
            make_uint4(f2tf32(ar1.x), f2tf32(ar1.y), f2tf32(ar1.z), f2tf32(ar1.w));
        #pragma unroll
        for (int it = 0; it < 2; it++)
            *(uint4*)&Bs[0][bnl][(kq2 + 2*it)*4] =
                make_uint4(f2tf32(bpre[it][0]), f2tf32(bpre[it][1]),
                           f2tf32(bpre[it][2]), f2tf32(bpre[it][3]));
    }
    __syncthreads();

    const int NT = K / TBK;
    for (int t = 0; t < NT; t++) {
        const int buf = t & 1;
        if (t + 1 < NT) {
            const int k0 = (t + 1) * TBK;
            ar0 = *(const float4*)(Ap + k0);
            ar1 = *(const float4*)(Ap + (size_t)64 * K + k0);
            #pragma unroll
            for (int it = 0; it < 2; it++) {
                const int k = k0 + (kq2 + 2*it) * 4;
                #pragma unroll
                for (int j = 0; j < 4; j++)
                    bpre[it][j] = Wp[(size_t)(k + j) * N];
            }
        }

        #pragma unroll
        for (int ks = 0; ks < 2; ks++) {
            const int k0 = ks * 8;
            unsigned af[2][4], bf[4][4];
            #pragma unroll
            for (int mt = 0; mt < 2; mt++)
                LDSM4(af[mt], sptr(&As[buf][warp_m + mt*16 + a_l8 + l7][k0 + a_l16]));
            #pragma unroll
            for (int ntp = 0; ntp < 4; ntp++)
                LDSM4(bf[ntp], sptr(&Bs[buf][warp_n + ntp*16 + b_l16 + l7][k0 + b_l8]));
            #pragma unroll
            for (int mt = 0; mt < 2; mt++)
                #pragma unroll
                for (int nt = 0; nt < 8; nt++)
                    MMA_TF32(acc[mt][nt], af[mt][0], af[mt][1], af[mt][2], af[mt][3],
                             bf[nt>>1][(nt&1)*2], bf[nt>>1][(nt&1)*2+1]);
        }

        if (t + 1 < NT) {
            const int nb = (t + 1) & 1;
            *(uint4*)&As[nb][arow][acol] =
                make_uint4(f2tf32(ar0.x), f2tf32(ar0.y), f2tf32(ar0.z), f2tf32(ar0.w));
            *(uint4*)&As[nb][arow+64][acol] =
                make_uint4(f2tf32(ar1.x), f2tf32(ar1.y), f2tf32(ar1.z), f2tf32(ar1.w));
            #pragma unroll
            for (int it = 0; it < 2; it++)
                *(uint4*)&Bs[nb][bnl][(kq2 + 2*it)*4] =
                    make_uint4(f2tf32(bpre[it][0]), f2tf32(bpre[it][1]),
                               f2tf32(bpre[it][2]), f2tf32(bpre[it][3]));
            __syncthreads();
        }
    }

    #pragma unroll
    for (int mt = 0; mt < 2; mt++) {
        #pragma unroll
        for (int nt = 0; nt < 8; nt++) {
            const int row0 = bm + warp_m + mt * 16 + gr;
            const int row1 = row0 + 8;
            const int col  = bn + warp_n + nt * 8 + gc * 2;
            const float b0 = bias[col], b1 = bias[col + 1];
            float v0 = acc[mt][nt][0] + b0;
            float v1 = acc[mt][nt][1] + b1;
            float v2 = acc[mt][nt][2] + b0;
            float v3 = acc[mt][nt][3] + b1;
            if (EPI == 0) {
                const float m0 = mask[row0], m1 = mask[row1];
                v0 *= m0; v1 *= m0; v2 *= m1; v3 *= m1;
            } else if (EPI == 2) {
                const float2 r0 = *(const float2*)(A + (size_t)row0 * K + col);
                const float2 r1 = *(const float2*)(A + (size_t)row1 * K + col);
                v0 = r0.x + fmaxf(v0, 0.f);
                v1 = r0.y + fmaxf(v1, 0.f);
                v2 = r1.x + fmaxf(v2, 0.f);
                v3 = r1.y + fmaxf(v3, 0.f);
            }
            *(float2*)&C[(size_t)row0 * N + col] = make_float2(v0, v1);
            *(float2*)&C[(size_t)row1 * N + col] = make_float2(v2, v3);
        }
    }
}

// ================= bf16 attention: full-strip warps, X in registers =================
// 8 warps, each owns 16 query rows x all 64 keys. K/V double-buffered, 1 barrier/tile.
#define SH 72
#define ATT_SMEM ((128*SH + 2*64*SH + 2*64*SH)*2 + (128 + 2*64)*4)

__global__ void __launch_bounds__(256, 2) attn_bf(
    const float* __restrict__ Qp, const float* __restrict__ Kp,
    const float* __restrict__ Vp, const float* __restrict__ Qm,
    const float* __restrict__ Km, float* __restrict__ O)
{
    extern __shared__ char smc[];
    __nv_bfloat16* Qs = (__nv_bfloat16*)smc;    // [128][SH]
    __nv_bfloat16* Ks = Qs + 128*SH;            // [2][64][SH]
    __nv_bfloat16* Vs = Ks + 2*64*SH;           // [2][64][SH]
    float* qms = (float*)(Vs + 2*64*SH);        // [128]
    float* kms = qms + 128;                     // [2][64]

    const int tid  = threadIdx.x;
    const int lane = tid & 31;
    const int wid  = tid >> 5;
    const int gr = lane >> 2, gc = lane & 3;
    const int l7  = lane & 7;
    const int l8  = (lane & 8)  ? 8 : 0;
    const int l16 = (lane & 16) ? 8 : 0;
    const int r0  = wid * 16;                   // this warp's query rows

    const int q0 = blockIdx.x * 128;
    const int b  = blockIdx.y;
    const int h  = blockIdx.z;
    const size_t base = (size_t)b * NQ * D_ + (size_t)h * DH;
    const float scale = 0.044194173824159216f;   // 1/sqrt(512)

    const int lrow = tid >> 4;          // 0..15
    const int lc4  = (tid & 15) * 4;    // 0..60

    // Q tile -> bf16 smem
    #pragma unroll
    for (int p = 0; p < 8; p++) {
        const int row = p * 16 + lrow;
        float4 v = *(const float4*)(Qp + base + (size_t)(q0 + row) * D_ + lc4);
        *(uint2*)&Qs[row*SH + lc4] = make_uint2(pkbf(v.x, v.y), pkbf(v.z, v.w));
    }
    if (tid < 128) qms[tid] = Qm[(size_t)b*NQ + q0 + tid];

    // prefetch K/V tile 0
    float4 kpre[4], vpre[4];
    #pragma unroll
    for (int p = 0; p < 4; p++) {
        const int row = p * 16 + lrow;
        kpre[p] = *(const float4*)(Kp + base + (size_t)row * D_ + lc4);
        vpre[p] = *(const float4*)(Vp + base + (size_t)row * D_ + lc4);
    }

    float oacc[8][4];
    #pragma unroll
    for (int nt = 0; nt < 8; nt++)
        #pragma unroll
        for (int c = 0; c < 4; c++) oacc[nt][c] = 0.f;
    float rsum0 = 0.f, rsum1 = 0.f;

    for (int kt = 0; kt < NQ/64; kt++) {
        const int buf = kt & 1;
        __nv_bfloat16* Kb = Ks + buf*64*SH;
        __nv_bfloat16* Vb = Vs + buf*64*SH;
        #pragma unroll
        for (int p = 0; p < 4; p++) {
            const int row = p * 16 + lrow;
            *(uint2*)&Kb[row*SH + lc4] = make_uint2(pkbf(kpre[p].x, kpre[p].y),
                                                    pkbf(kpre[p].z, kpre[p].w));
            *(uint2*)&Vb[row*SH + lc4] = make_uint2(pkbf(vpre[p].x, vpre[p].y),
                                                    pkbf(vpre[p].z, vpre[p].w));
        }
        if (tid < 64) kms[buf*64 + tid] = Km[(size_t)b*NQ + kt*64 + tid];
        __syncthreads();

        if (kt + 1 < NQ/64) {
            #pragma unroll
            for (int p = 0; p < 4; p++)
                kpre[p] = *(const float4*)(Kp + base +
                    (size_t)((kt+1)*64 + p*16 + lrow) * D_ + lc4);
        }

        // ---- S = Q.K^T : warp computes [16 rows][64 keys] ----
        float sacc[8][4];
        #pragma unroll
        for (int nt = 0; nt < 8; nt++)
            #pragma unroll
            for (int c = 0; c < 4; c++) sacc[nt][c] = 0.f;

        #pragma unroll
        for (int ks = 0; ks < 4; ks++) {
            unsigned qf[4], bq[4][4];
            LDSM4(qf, sptr(&Qs[(r0 + l7 + l8)*SH + ks*16 + l16]));
            #pragma unroll
            for (int ntp = 0; ntp < 4; ntp++)
                LDSM4(bq[ntp], sptr(&Kb[(ntp*16 + l7 + l16)*SH + ks*16 + l8]));
            #pragma unroll
            for (int nt = 0; nt < 8; nt++)
                MMA_BF16(sacc[nt], qf, bq[nt>>1][(nt&1)*2], bq[nt>>1][(nt&1)*2+1]);
        }

        if (kt + 1 < NQ/64) {
            #pragma unroll
            for (int p = 0; p < 4; p++)
                vpre[p] = *(const float4*)(Vp + base +
                    (size_t)((kt+1)*64 + p*16 + lrow) * D_ + lc4);
        }

        // ---- double-exp transform in registers; X frags in-lane ----
        unsigned xf[4][4];
        const float qm0 = qms[r0 + gr];
        const float qm1 = qms[r0 + 8 + gr];
        float p0 = 0.f, p1 = 0.f;
        #pragma unroll
        for (int nt = 0; nt < 8; nt++) {
            const int col = nt*8 + gc*2;
            const float km0 = kms[buf*64 + col];
            const float km1 = kms[buf*64 + col + 1];
            float x00 = __expf(__expf(sacc[nt][0]*scale) * km0) * qm0;
            float x01 = __expf(__expf(sacc[nt][1]*scale) * km1) * qm0;
            float x10 = __expf(__expf(sacc[nt][2]*scale) * km0) * qm1;
            float x11 = __expf(__expf(sacc[nt][3]*scale) * km1) * qm1;
            p0 += x00 + x01;
            p1 += x10 + x11;
            const int ksv = nt >> 1, pr = (nt & 1) * 2;
            xf[ksv][pr]     = pkbf(x00, x01);
            xf[ksv][pr + 1] = pkbf(x10, x11);
        }
        p0 += __shfl_xor_sync(0xffffffffu, p0, 1);
        p0 += __shfl_xor_sync(0xffffffffu, p0, 2);
        p1 += __shfl_xor_sync(0xffffffffu, p1, 1);
        p1 += __shfl_xor_sync(0xffffffffu, p1, 2);
        rsum0 += p0;
        rsum1 += p1;

        // ---- O += X.V ----
        #pragma unroll
        for (int ksv = 0; ksv < 4; ksv++) {
            unsigned bv[4][4];
            #pragma unroll
            for (int ntp = 0; ntp < 4; ntp++)
                LDSM4T(bv[ntp], sptr(&Vb[(ksv*16 + l7 + l8)*SH + ntp*16 + l16]));
            #pragma unroll
            for (int nt = 0; nt < 8; nt++)
                MMA_BF16(oacc[nt], xf[ksv], bv[nt>>1][(nt&1)*2], bv[nt>>1][(nt&1)*2+1]);
        }
    }

    // ---- epilogue: O = Qp + oacc / (rowsum + 1e-8), rows warp-private ----
    const float inv0 = 1.f / (rsum0 + 1e-8f);
    const float inv1 = 1.f / (rsum1 + 1e-8f);
    const int row0 = q0 + r0 + gr;
    const int row1 = row0 + 8;
    #pragma unroll
    for (int nt = 0; nt < 8; nt++) {
        const int col = nt*8 + gc*2;
        const float2 q0v = *(const float2*)(Qp + base + (size_t)row0*D_ + col);
        const float2 q1v = *(const float2*)(Qp + base + (size_t)row1*D_ + col);
        *(float2*)&O[base + (size_t)row0*D_ + col] =
            make_float2(q0v.x + oacc[nt][0]*inv0, q0v.y + oacc[nt][1]*inv0);
        *(float2*)&O[base + (size_t)row1*D_ + col] =
            make_float2(q1v.x + oacc[nt][2]*inv1, q1v.y + oacc[nt][3]*inv1);
    }
}

// ================= LayerNorm =================
__global__ void __launch_bounds__(128) ln_k(
    const float* __restrict__ X, const float* __restrict__ g,
    const float* __restrict__ bb, float* __restrict__ Y)
{
    const int row = blockIdx.x;
    const int t = threadIdx.x;
    const float4 v = *(const float4*)(X + (size_t)row*D_ + 4*t);
    float s  = v.x + v.y + v.z + v.w;
    float s2 = v.x*v.x + v.y*v.y + v.z*v.z + v.w*v.w;
    #pragma unroll
    for (int o = 16; o > 0; o >>= 1) {
        s  += __shfl_xor_sync(0xffffffffu, s,  o);
        s2 += __shfl_xor_sync(0xffffffffu, s2, o);
    }
    __shared__ float ws[4], ws2[4];
    if ((t & 31) == 0) { ws[t>>5] = s; ws2[t>>5] = s2; }
    __syncthreads();
    s  = ws[0]  + ws[1]  + ws[2]  + ws[3];
    s2 = ws2[0] + ws2[1] + ws2[2] + ws2[3];
    const float mean = s * (1.f/D_);
    const float var  = s2 * (1.f/D_) - mean*mean;
    const float inv  = rsqrtf(var + 1e-5f);
    const float4 gv = *(const float4*)(g  + 4*t);
    const float4 bv = *(const float4*)(bb + 4*t);
    float4 o;
    o.x = (v.x - mean)*inv*gv.x + bv.x;
    o.y = (v.y - mean)*inv*gv.y + bv.y;
    o.z = (v.z - mean)*inv*gv.z + bv.z;
    o.w = (v.w - mean)*inv*gv.w + bv.w;
    *(float4*)(Y + (size_t)row*D_ + 4*t) = o;
}

extern "C" void kernel_launch(void* const* d_in, const int* in_sizes, int n_in,
                              void* d_out, int out_size)
{
    const float* Q  = (const float*)d_in[0];
    const float* K  = (const float*)d_in[1];
    const float* Qm = (const float*)d_in[2];
    const float* Km = (const float*)d_in[3];
    const float* Wq = (const float*)d_in[4];
    const float* bq = (const float*)d_in[5];
    const float* Wk = (const float*)d_in[6];
    const float* bk = (const float*)d_in[7];
    const float* Wv = (const float*)d_in[8];
    const float* bv = (const float*)d_in[9];
    const float* Wo = (const float*)d_in[10];
    const float* bo = (const float*)d_in[11];
    const float* g0 = (const float*)d_in[12];
    const float* b0 = (const float*)d_in[13];
    const float* g1 = (const float*)d_in[14];
    const float* b1 = (const float*)d_in[15];
    float* out = (float*)d_out;

    float *pQp, *pKp, *pV, *pO1, *pO2;
    cudaGetSymbolAddress((void**)&pQp, g_Qp);
    cudaGetSymbolAddress((void**)&pKp, g_Kp);
    cudaGetSymbolAddress((void**)&pV,  g_V);
    cudaGetSymbolAddress((void**)&pO1, g_O1);
    cudaGetSymbolAddress((void**)&pO2, g_O2);

    cudaFuncSetAttribute(attn_bf, cudaFuncAttributeMaxDynamicSharedMemorySize, ATT_SMEM);

    dim3 gblk(256);
    dim3 ggrid(D_/TBN, M_/TBM);

    gemm_tc<0><<<ggrid, gblk>>>(Q, Wq, bq, Qm, pQp, M_, D_, D_);
    gemm_tc<0><<<ggrid, gblk>>>(K, Wk, bk, Km, pKp, M_, D_, D_);
    gemm_tc<1><<<ggrid, gblk>>>(K, Wv, bv, nullptr, pV, M_, D_, D_);

    dim3 agrid(NQ/128, B_, H_);
    attn_bf<<<agrid, 256, ATT_SMEM>>>(pQp, pKp, pV, Qm, Km, pO1);

    ln_k<<<M_, 128>>>(pO1, g0, b0, pO2);
    gemm_tc<2><<<ggrid, gblk>>>(pO2, Wo, bo, nullptr, pQp, M_, D_, D_);
    ln_k<<<M_, 128>>>(pQp, g1, b1, out);
}